// round 3
// baseline (speedup 1.0000x reference)
#include <cuda_runtime.h>

// Deformable Conv3d, fp32 — barrier-free warp-autonomous version.
// prep: x -> channels-last xT[b][spatial][c]; weight -> wT[k][c][o].
// deform: warp = 4 points x 64 outs, fully independent (no smem, no barriers).
//   Per k:
//     params: each lane OWNS one (point, corner) pair -> computes (byteoff, wgt) once
//     gather: 16 iters, params via shfl, coalesced 256B channel-vector LDG.128
//     GEMM:   s via shfl from sampling regs, w via direct LDG (L1-hot),
//             packed fma.rn.f32x2 over point-pairs.

namespace {
constexpr int B_    = 2;
constexpr int CIN_  = 64;
constexpr int COUT_ = 64;
constexpr int D_    = 8;
constexpr int H_    = 32;
constexpr int W_    = 32;
constexpr int K_    = 27;
constexpr int P_    = D_ * H_ * W_;   // 8192
constexpr int TP    = 32;             // points per block (8 warps x 4)
constexpr int THREADS = 256;
constexpr unsigned FULL = 0xffffffffu;
}

__device__ float g_xT[B_ * P_ * CIN_];       // [b][spatial][c]
__device__ float g_wT[K_ * CIN_ * COUT_];    // [k][c][o]

__device__ __forceinline__ unsigned long long pk2(float x, float y) {
    unsigned long long r;
    asm("mov.b64 %0, {%1, %2};" : "=l"(r) : "f"(x), "f"(y));
    return r;
}
__device__ __forceinline__ float2 upk(unsigned long long v) {
    float2 f;
    asm("mov.b64 {%0, %1}, %2;" : "=f"(f.x), "=f"(f.y) : "l"(v));
    return f;
}
__device__ __forceinline__ void ffma2(unsigned long long& d,
                                      unsigned long long a,
                                      unsigned long long b) {
    asm("fma.rn.f32x2 %0, %1, %2, %0;" : "+l"(d) : "l"(a), "l"(b));
}

__global__ void prep_kernel(const float* __restrict__ x,
                            const float* __restrict__ w) {
    int stride = gridDim.x * blockDim.x;
    int tid = blockIdx.x * blockDim.x + threadIdx.x;
    for (int i = tid; i < B_ * CIN_ * P_; i += stride) {
        int s = i % P_;
        int c = (i / P_) % CIN_;
        int b = i / (P_ * CIN_);
        g_xT[(b * P_ + s) * CIN_ + c] = x[i];
    }
    for (int i = tid; i < COUT_ * CIN_ * K_; i += stride) {
        int k = i % K_;
        int c = (i / K_) % CIN_;
        int o = i / (K_ * CIN_);
        g_wT[(k * CIN_ + c) * COUT_ + o] = w[i];
    }
}

__global__ __launch_bounds__(THREADS)
void deform_kernel(const float* __restrict__ offset,
                   const float* __restrict__ bias,
                   float* __restrict__ out) {
    const int tid  = threadIdx.x;
    const int lane = tid & 31;
    const int warp = tid >> 5;
    const int blk  = blockIdx.x;
    const int b    = blk >> 8;
    const int p0   = (blk & 255) * TP;

    const float* offB = offset + (size_t)b * 3 * K_ * P_;
    const char*  xTbB = reinterpret_cast<const char*>(g_xT + (size_t)b * P_ * CIN_);

    const int plb = warp * 4;            // warp's 4 points: p0+plb .. +3
    const int pb  = p0 + plb;

    // ---- this lane's owned (point, corner) pair ----
    const int i_own  = (lane >> 2) & 3;          // point index 0..3
    const int jj_own = lane & 3;                 // corner slot within half
    const int h_own  = lane >> 4;                // half
    const int j_own  = jj_own * 2 + h_own;       // corner 0..7
    const int dd = (j_own >> 2) & 1, dh = (j_own >> 1) & 1, dw = j_own & 1;

    const int p_own  = pb + i_own;
    const int od = p_own >> 10;
    const int oh = (p_own >> 5) & 31;
    const int ow = p_own & 31;

    const int half = lane >> 4;                  // gather role
    const int c4   = lane & 15;

    unsigned long long acc00 = 0ull, acc01 = 0ull;   // out o0: (p0,p1),(p2,p3)
    unsigned long long acc10 = 0ull, acc11 = 0ull;   // out o1

    const float* wkbase = g_wT;

    for (int k = 0; k < K_; k++) {
        const int kd = k / 9, kh = (k / 3) % 3, kw = k % 3;

        // ---- params: one (point,corner) per lane ----
        const float* offk = offB + 3 * k * P_;
        float zd = (float)(od - 1 + kd) + __ldg(&offk[0 * P_ + p_own]);
        float zh = (float)(oh - 1 + kh) + __ldg(&offk[1 * P_ + p_own]);
        float zw = (float)(ow - 1 + kw) + __ldg(&offk[2 * P_ + p_own]);
        float fd = floorf(zd), fh = floorf(zh), fw = floorf(zw);
        int d0 = (int)fd, h0 = (int)fh, w0 = (int)fw;
        float rd = zd - fd, rh = zh - fh, rw = zw - fw;

        int di = d0 + dd, hi = h0 + dh, wi = w0 + dw;
        bool valid = (di >= 0) & (di < D_) & (hi >= 0) & (hi < H_) &
                     (wi >= 0) & (wi < W_);
        float wgt = (dd ? rd : 1.f - rd) * (dh ? rh : 1.f - rh) *
                    (dw ? rw : 1.f - rw);
        wgt = valid ? wgt : 0.f;
        int dic = min(max(di, 0), D_ - 1);
        int hic = min(max(hi, 0), H_ - 1);
        int wic = min(max(wi, 0), W_ - 1);
        int bo = (((dic * H_ + hic) * W_ + wic) * CIN_) * 4;  // byte offset

        // ---- gather: all lanes fetch channel chunk c4 for (point i2, its half's corners) ----
        float4 a[4];
#pragma unroll
        for (int i2 = 0; i2 < 4; i2++) a[i2] = make_float4(0.f, 0.f, 0.f, 0.f);

#pragma unroll
        for (int i2 = 0; i2 < 4; i2++) {
#pragma unroll
            for (int jj2 = 0; jj2 < 4; jj2++) {
                int src = (lane & 16) | (i2 * 4 + jj2);
                int   bos = __shfl_sync(FULL, bo, src);
                float wgs = __shfl_sync(FULL, wgt, src);
                float4 v = __ldg(reinterpret_cast<const float4*>(
                                     xTbB + bos + (c4 << 4)));
                a[i2].x += wgs * v.x; a[i2].y += wgs * v.y;
                a[i2].z += wgs * v.z; a[i2].w += wgs * v.w;
            }
        }
        // combine halves -> lanes 0..15 hold final s[point][c4*4..+3]
#pragma unroll
        for (int i2 = 0; i2 < 4; i2++) {
            a[i2].x += __shfl_down_sync(FULL, a[i2].x, 16);
            a[i2].y += __shfl_down_sync(FULL, a[i2].y, 16);
            a[i2].z += __shfl_down_sync(FULL, a[i2].z, 16);
            a[i2].w += __shfl_down_sync(FULL, a[i2].w, 16);
        }

        // ---- GEMM: lane = out pair (lane, lane+32), packed over point pairs ----
        const float* wk = wkbase + k * (CIN_ * COUT_);
#pragma unroll
        for (int q = 0; q < 16; q++) {
#pragma unroll
            for (int r = 0; r < 4; r++) {
                const int c = q * 4 + r;
                float s0 = __shfl_sync(FULL, (&a[0].x)[r], q);
                float s1 = __shfl_sync(FULL, (&a[1].x)[r], q);
                float s2 = __shfl_sync(FULL, (&a[2].x)[r], q);
                float s3 = __shfl_sync(FULL, (&a[3].x)[r], q);
                unsigned long long s01 = pk2(s0, s1);
                unsigned long long s23 = pk2(s2, s3);
                float w0 = __ldg(&wk[c * COUT_ + lane]);
                float w1 = __ldg(&wk[c * COUT_ + lane + 32]);
                unsigned long long w0p = pk2(w0, w0);
                unsigned long long w1p = pk2(w1, w1);
                ffma2(acc00, w0p, s01);
                ffma2(acc01, w0p, s23);
                ffma2(acc10, w1p, s01);
                ffma2(acc11, w1p, s23);
            }
        }
    }

    // ---- epilogue ----
    const float b0 = __ldg(&bias[lane]);
    const float b1 = __ldg(&bias[lane + 32]);
    float2 r00 = upk(acc00), r01 = upk(acc01);
    float2 r10 = upk(acc10), r11 = upk(acc11);
    r00.x += b0; r00.y += b0; r01.x += b0; r01.y += b0;
    r10.x += b1; r10.y += b1; r11.x += b1; r11.y += b1;

    float* row0 = out + ((size_t)b * COUT_ + lane) * P_ + pb;
    float* row1 = out + ((size_t)b * COUT_ + lane + 32) * P_ + pb;
    *reinterpret_cast<float2*>(row0)     = r00;
    *reinterpret_cast<float2*>(row0 + 2) = r01;
    *reinterpret_cast<float2*>(row1)     = r10;
    *reinterpret_cast<float2*>(row1 + 2) = r11;
}

extern "C" void kernel_launch(void* const* d_in, const int* in_sizes, int n_in,
                              void* d_out, int out_size) {
    const float* x      = (const float*)d_in[0];
    const float* offset = (const float*)d_in[1];
    const float* weight = (const float*)d_in[2];
    const float* bias   = (const float*)d_in[3];
    float* out = (float*)d_out;

    prep_kernel<<<256, THREADS>>>(x, weight);
    deform_kernel<<<B_ * (P_ / TP), THREADS>>>(offset, bias, out);
}